// round 16
// baseline (speedup 1.0000x reference)
#include <cuda_runtime.h>

#define N_LAYERS 32
#define N_EV     64          // activation events (32 fwd + 32 inv)
#define N_SUB    8
#define TPB      128
#define EPT      6

// Blob of composed constants: per-event {Lc0, Lc1, mc, g0}, per-event g1, final 2 rows.
struct ConstBlob {
    float4 ev[N_EV];
    float  g1[N_EV];
    float4 fin[2];
};

__constant__ ConstBlob c_blob;

__device__ __forceinline__ float tanh_fast(float x) {
    float y;
    asm("tanh.approx.f32 %0, %1;" : "=f"(y) : "f"(x));
    return y;
}

// Compose layer i's (bias then 8 shears) into forward affine v' = M v + c.
__device__ __forceinline__ void compose_fwd(const float* bias_b, const float* lin_w,
                                            int i, float M[4], float c[2]) {
    float m00 = 1.f, m01 = 0.f, m10 = 0.f, m11 = 1.f;
    float c0 = bias_b[2 * i + 0];
    float c1 = bias_b[2 * i + 1];
    #pragma unroll
    for (int j = 0; j < N_SUB; ++j) {
        float w = lin_w[i * N_SUB + j];
        if ((j & 1) == 0) {          // q += w*p
            m00 = fmaf(w, m10, m00);
            m01 = fmaf(w, m11, m01);
            c0  = fmaf(w, c1,  c0);
        } else {                      // p += w*q
            m10 = fmaf(w, m00, m10);
            m11 = fmaf(w, m01, m11);
            c1  = fmaf(w, c0,  c1);
        }
    }
    M[0] = m00; M[1] = m01; M[2] = m10; M[3] = m11;
    c[0] = c0;  c[1] = c1;
}

// Inverse affine of layer i: v = U w + d (reversed negated shears; d = -bias).
__device__ __forceinline__ void compose_inv(const float* bias_b, const float* lin_w,
                                            int i, float U[4], float d[2]) {
    float u00 = 1.f, u01 = 0.f, u10 = 0.f, u11 = 1.f;
    #pragma unroll
    for (int j = N_SUB - 1; j >= 0; --j) {
        float w = lin_w[i * N_SUB + j];
        if ((j & 1) == 0) {          // q -= w*p
            u00 = fmaf(-w, u10, u00);
            u01 = fmaf(-w, u11, u01);
        } else {                      // p -= w*q
            u10 = fmaf(-w, u00, u10);
            u11 = fmaf(-w, u01, u11);
        }
    }
    U[0] = u00; U[1] = u01; U[2] = u10; U[3] = u11;
    d[0] = -bias_b[2 * i + 0];
    d[1] = -bias_b[2 * i + 1];
}

// One block of 64 threads: compose raw affines, build event pre-affines,
// scan to cumulative (L, m), write runtime constants DIRECTLY into the
// constant-memory backing store (out = generic pointer to c_blob).
__global__ void setup_kernel(const float* __restrict__ act_w,
                             const float* __restrict__ bias_b,
                             const float* __restrict__ lin_w,
                             ConstBlob*   __restrict__ out)
{
    __shared__ float4 sA[N_EV];
    __shared__ float2 sB[N_EV];

    const int t = threadIdx.x;

    // Step 1: raw per-layer affines. fwd i -> slot i, inv i -> slot 32+i.
    if (t < 32) {
        float M[4], c[2];
        compose_fwd(bias_b, lin_w, t, M, c);
        sA[t] = make_float4(M[0], M[1], M[2], M[3]);
        sB[t] = make_float2(c[0], c[1]);
    } else {
        float U[4], d[2];
        compose_inv(bias_b, lin_w, t - 32, U, d);
        sA[t] = make_float4(U[0], U[1], U[2], U[3]);
        sB[t] = make_float2(d[0], d[1]);
    }
    __syncthreads();

    // Step 2: event pre-affines P_k.
    // k=0: I.  1<=k<=31: M_{k-1}.  k=32: U_31 ∘ R ∘ M_31 (R = diag(1,-1)).
    // 33<=k<=63: U_{63-k}.
    float4 P = make_float4(1.f, 0.f, 0.f, 1.f);
    float2 Pb = make_float2(0.f, 0.f);
    if (t >= 1 && t <= 31) {
        P = sA[t - 1]; Pb = sB[t - 1];
    } else if (t == 32) {
        float4 M = sA[31]; float2 c = sB[31];
        float4 RM = make_float4(M.x, M.y, -M.z, -M.w);
        float2 Rc = make_float2(c.x, -c.y);
        float4 U = sA[63]; float2 d = sB[63];
        P.x = U.x * RM.x + U.y * RM.z;  P.y = U.x * RM.y + U.y * RM.w;
        P.z = U.z * RM.x + U.w * RM.z;  P.w = U.z * RM.y + U.w * RM.w;
        Pb.x = U.x * Rc.x + U.y * Rc.y + d.x;
        Pb.y = U.z * Rc.x + U.w * Rc.y + d.y;
    } else if (t >= 33) {
        int i = 63 - t;
        P = sA[32 + i]; Pb = sB[32 + i];
    }
    __syncthreads();
    sA[t] = P; sB[t] = Pb;
    __syncthreads();

    // Step 3: inclusive scan, L^(k) = P_k ∘ ... ∘ P_0.
    #pragma unroll
    for (int dstep = 1; dstep < N_EV; dstep <<= 1) {
        float4 Ao; float2 bo;
        bool active = (t >= dstep);
        if (active) { Ao = sA[t - dstep]; bo = sB[t - dstep]; }
        __syncthreads();
        if (active) {
            float4 An = sA[t]; float2 bn = sB[t];
            float4 Rm;
            Rm.x = An.x * Ao.x + An.y * Ao.z;  Rm.y = An.x * Ao.y + An.y * Ao.w;
            Rm.z = An.z * Ao.x + An.w * Ao.z;  Rm.w = An.z * Ao.y + An.w * Ao.w;
            float2 rb;
            rb.x = An.x * bo.x + An.y * bo.y + bn.x;
            rb.y = An.z * bo.x + An.w * bo.y + bn.y;
            sA[t] = Rm; sB[t] = rb;
        }
        __syncthreads();
    }

    // Step 4: runtime constants, written straight into constant-memory backing.
    {
        float4 L = sA[t]; float2 m = sB[t];
        int i = (t < 32) ? t : (63 - t);
        float a = act_w[i];
        float alpha = (t < 32) ? a : -a;
        int e = (i & 1);
        float Lc0, Lc1, mc;
        if (e == 0) { Lc0 = L.z; Lc1 = L.w; mc = m.y; }   // arg = p-component
        else        { Lc0 = L.x; Lc1 = L.y; mc = m.x; }   // arg = q-component
        float det = L.x * L.w - L.y * L.z;
        float sc = alpha / det;
        float g0, g1;
        if (e == 0) { g0 =  sc * L.w; g1 = -sc * L.z; }
        else        { g0 = -sc * L.y; g1 =  sc * L.x; }
        out->ev[t] = make_float4(Lc0, Lc1, mc, g0);
        out->g1[t] = g1;
        if (t == 63) {
            // out = diag(1,-1)·(L z + m)
            out->fin[0] = make_float4( L.x,  L.y,  m.x, 0.f);
            out->fin[1] = make_float4(-L.z, -L.w, -m.y, 0.f);
        }
    }
}

__global__ __launch_bounds__(TPB, 10)
void sympnet_kernel(const float2* __restrict__ x,
                    float2*       __restrict__ out,
                    int n)
{
    const int base = blockIdx.x * (TPB * EPT) + threadIdx.x;

    float z0[EPT], z1[EPT];
    #pragma unroll
    for (int e = 0; e < EPT; ++e) {
        int idx = base + e * TPB;
        if (idx < n) {
            float2 v = x[idx];
            z0[e] = v.x; z1[e] = v.y;
        } else {
            z0[e] = 0.f; z1[e] = 0.f;
        }
    }

    // 64 activation events: arg = Lc·z + mc ; z += tanh(arg) * g
    #pragma unroll 4
    for (int k = 0; k < N_EV; ++k) {
        float4 cc = c_blob.ev[k];
        float g1 = c_blob.g1[k];
        #pragma unroll
        for (int e = 0; e < EPT; ++e) {
            float arg = fmaf(cc.x, z0[e], fmaf(cc.y, z1[e], cc.z));
            float th = tanh_fast(arg);
            z0[e] = fmaf(cc.w, th, z0[e]);
            z1[e] = fmaf(g1,  th, z1[e]);
        }
    }

    // final affine + store (output signs folded in)
    float4 f0 = c_blob.fin[0];
    float4 f1 = c_blob.fin[1];
    #pragma unroll
    for (int e = 0; e < EPT; ++e) {
        int idx = base + e * TPB;
        if (idx < n) {
            float qo = fmaf(f0.x, z0[e], fmaf(f0.y, z1[e], f0.z));
            float po = fmaf(f1.x, z0[e], fmaf(f1.y, z1[e], f1.z));
            out[idx] = make_float2(qo, po);
        }
    }
}

extern "C" void kernel_launch(void* const* d_in, const int* in_sizes, int n_in,
                              void* d_out, int out_size)
{
    const float2* x     = (const float2*)d_in[0];
    const float*  act_w = (const float*)d_in[1];
    const float*  bias_b= (const float*)d_in[2];
    const float*  lin_w = (const float*)d_in[3];
    float2* out = (float2*)d_out;

    int n = in_sizes[0] / 2;   // number of (q,p) pairs

    // Generic device pointer to the constant-memory blob (no alloc; pure query).
    void* c_ptr = nullptr;
    cudaGetSymbolAddress(&c_ptr, c_blob);

    // 1. compose event constants, writing directly into constant backing store
    setup_kernel<<<1, N_EV>>>(act_w, bias_b, lin_w, (ConstBlob*)c_ptr);

    // 2. main kernel (reads c_blob via the constant cache, freshly invalidated
    //    at this launch boundary)
    int per_block = TPB * EPT;
    int blocks = (n + per_block - 1) / per_block;
    sympnet_kernel<<<blocks, TPB>>>(x, out, n);
}

// round 17
// speedup vs baseline: 1.0077x; 1.0077x over previous
#include <cuda_runtime.h>

#define N_LAYERS 32
#define N_EV     64          // activation events (32 fwd + 32 inv)
#define N_SUB    8
#define TPB      128
#define EPT      8           // elements (pairs) per thread; grid = 1024 exactly

__device__ __forceinline__ float tanh_fast(float x) {
    float y;
    asm("tanh.approx.f32 %0, %1;" : "=f"(y) : "f"(x));
    return y;
}

// Compose layer i's (bias then 8 shears) into forward affine v' = M v + c.
__device__ __forceinline__ void compose_fwd(const float* bias_b, const float* lin_w,
                                            int i, float M[4], float c[2]) {
    float m00 = 1.f, m01 = 0.f, m10 = 0.f, m11 = 1.f;
    float c0 = bias_b[2 * i + 0];
    float c1 = bias_b[2 * i + 1];
    #pragma unroll
    for (int j = 0; j < N_SUB; ++j) {
        float w = lin_w[i * N_SUB + j];
        if ((j & 1) == 0) {          // q += w*p
            m00 = fmaf(w, m10, m00);
            m01 = fmaf(w, m11, m01);
            c0  = fmaf(w, c1,  c0);
        } else {                      // p += w*q
            m10 = fmaf(w, m00, m10);
            m11 = fmaf(w, m01, m11);
            c1  = fmaf(w, c0,  c1);
        }
    }
    M[0] = m00; M[1] = m01; M[2] = m10; M[3] = m11;
    c[0] = c0;  c[1] = c1;
}

// Inverse affine of layer i: v = U w + d (reversed negated shears; d = -bias).
__device__ __forceinline__ void compose_inv(const float* bias_b, const float* lin_w,
                                            int i, float U[4], float d[2]) {
    float u00 = 1.f, u01 = 0.f, u10 = 0.f, u11 = 1.f;
    #pragma unroll
    for (int j = N_SUB - 1; j >= 0; --j) {
        float w = lin_w[i * N_SUB + j];
        if ((j & 1) == 0) {          // q -= w*p
            u00 = fmaf(-w, u10, u00);
            u01 = fmaf(-w, u11, u01);
        } else {                      // p -= w*q
            u10 = fmaf(-w, u00, u10);
            u11 = fmaf(-w, u01, u11);
        }
    }
    U[0] = u00; U[1] = u01; U[2] = u10; U[3] = u11;
    d[0] = -bias_b[2 * i + 0];
    d[1] = -bias_b[2 * i + 1];
}

__global__ __launch_bounds__(TPB, 10)
void sympnet_kernel(const float4* __restrict__ x4,
                    const float*  __restrict__ act_w,
                    const float*  __restrict__ bias_b,
                    const float*  __restrict__ lin_w,
                    float4*       __restrict__ out4,
                    int n4)            // count of float4 (= 2 pairs each)
{
    // Prologue (per block): compose raw affines, build event pre-affines,
    // scan to cumulative (L^k, m^k), emit per-event runtime constants.
    __shared__ float4 sA[N_EV];
    __shared__ float2 sB[N_EV];
    __shared__ float4 s_ev[N_EV];    // {Lc0, Lc1, mc, g0}
    __shared__ float  s_g1[N_EV];
    __shared__ float4 s_fin[2];

    const int t = threadIdx.x;

    // Step 1: raw per-layer affines. fwd i -> slot i, inv i -> slot 32+i.
    if (t < 32) {
        float M[4], c[2];
        compose_fwd(bias_b, lin_w, t, M, c);
        sA[t] = make_float4(M[0], M[1], M[2], M[3]);
        sB[t] = make_float2(c[0], c[1]);
    } else if (t < 64) {
        float U[4], d[2];
        compose_inv(bias_b, lin_w, t - 32, U, d);
        sA[t] = make_float4(U[0], U[1], U[2], U[3]);
        sB[t] = make_float2(d[0], d[1]);
    }
    __syncthreads();

    // Step 2: event pre-affines P_k.
    // k=0: I.  1<=k<=31: M_{k-1}.  k=32: U_31 ∘ R ∘ M_31 (R = diag(1,-1)).
    // 33<=k<=63: U_{63-k}.
    float4 P = make_float4(1.f, 0.f, 0.f, 1.f);
    float2 Pb = make_float2(0.f, 0.f);
    if (t >= 1 && t <= 31) {
        P = sA[t - 1]; Pb = sB[t - 1];
    } else if (t == 32) {
        float4 M = sA[31]; float2 c = sB[31];
        float4 RM = make_float4(M.x, M.y, -M.z, -M.w);
        float2 Rc = make_float2(c.x, -c.y);
        float4 U = sA[63]; float2 d = sB[63];
        P.x = U.x * RM.x + U.y * RM.z;  P.y = U.x * RM.y + U.y * RM.w;
        P.z = U.z * RM.x + U.w * RM.z;  P.w = U.z * RM.y + U.w * RM.w;
        Pb.x = U.x * Rc.x + U.y * Rc.y + d.x;
        Pb.y = U.z * Rc.x + U.w * Rc.y + d.y;
    } else if (t >= 33 && t < 64) {
        int i = 63 - t;
        P = sA[32 + i]; Pb = sB[32 + i];
    }
    __syncthreads();
    if (t < N_EV) { sA[t] = P; sB[t] = Pb; }
    __syncthreads();

    // Step 3: inclusive scan, L^(k) = P_k ∘ ... ∘ P_0.
    #pragma unroll
    for (int dstep = 1; dstep < N_EV; dstep <<= 1) {
        float4 Ao; float2 bo;
        bool active = (t < N_EV) && (t >= dstep);
        if (active) { Ao = sA[t - dstep]; bo = sB[t - dstep]; }
        __syncthreads();
        if (active) {
            float4 An = sA[t]; float2 bn = sB[t];
            float4 Rm;
            Rm.x = An.x * Ao.x + An.y * Ao.z;  Rm.y = An.x * Ao.y + An.y * Ao.w;
            Rm.z = An.z * Ao.x + An.w * Ao.z;  Rm.w = An.z * Ao.y + An.w * Ao.w;
            float2 rb;
            rb.x = An.x * bo.x + An.y * bo.y + bn.x;
            rb.y = An.z * bo.x + An.w * bo.y + bn.y;
            sA[t] = Rm; sB[t] = rb;
        }
        __syncthreads();
    }

    // Step 4: per-event runtime constants.
    if (t < N_EV) {
        float4 L = sA[t]; float2 m = sB[t];
        int i = (t < 32) ? t : (63 - t);
        float a = act_w[i];
        float alpha = (t < 32) ? a : -a;
        int e = (i & 1);                 // even layer: arg = p-row; odd: arg = q-row
        float Lc0, Lc1, mc;
        if (e == 0) { Lc0 = L.z; Lc1 = L.w; mc = m.y; }
        else        { Lc0 = L.x; Lc1 = L.y; mc = m.x; }
        float det = L.x * L.w - L.y * L.z;
        float sc = alpha / det;
        float g0, g1;
        if (e == 0) { g0 =  sc * L.w; g1 = -sc * L.z; }
        else        { g0 = -sc * L.y; g1 =  sc * L.x; }
        s_ev[t] = make_float4(Lc0, Lc1, mc, g0);
        s_g1[t] = g1;
        if (t == 63) {
            // out = diag(1,-1)·(L z + m)
            s_fin[0] = make_float4( L.x,  L.y,  m.x, 0.f);
            s_fin[1] = make_float4(-L.z, -L.w, -m.y, 0.f);
        }
    }
    __syncthreads();

    // ---- main: EPT pairs per thread, loaded as EPT/2 float4 ----
    const int base4 = blockIdx.x * (TPB * (EPT / 2)) + t;

    float z0[EPT], z1[EPT];
    #pragma unroll
    for (int v = 0; v < EPT / 2; ++v) {
        int idx = base4 + v * TPB;
        if (idx < n4) {
            float4 d = x4[idx];           // {q0, p0, q1, p1}
            z0[2 * v + 0] = d.x; z1[2 * v + 0] = d.y;
            z0[2 * v + 1] = d.z; z1[2 * v + 1] = d.w;
        } else {
            z0[2 * v + 0] = 0.f; z1[2 * v + 0] = 0.f;
            z0[2 * v + 1] = 0.f; z1[2 * v + 1] = 0.f;
        }
    }

    // 64 activation events: arg = Lc·z + mc ; z += tanh(arg) * g
    #pragma unroll 4
    for (int k = 0; k < N_EV; ++k) {
        float4 cc = s_ev[k];
        float g1 = s_g1[k];
        #pragma unroll
        for (int e = 0; e < EPT; ++e) {
            float arg = fmaf(cc.x, z0[e], fmaf(cc.y, z1[e], cc.z));
            float th = tanh_fast(arg);
            z0[e] = fmaf(cc.w, th, z0[e]);
            z1[e] = fmaf(g1,  th, z1[e]);
        }
    }

    // final affine + store (output signs folded in)
    float4 f0 = s_fin[0];
    float4 f1 = s_fin[1];
    #pragma unroll
    for (int v = 0; v < EPT / 2; ++v) {
        int idx = base4 + v * TPB;
        if (idx < n4) {
            int e0 = 2 * v, e1 = 2 * v + 1;
            float4 d;
            d.x = fmaf(f0.x, z0[e0], fmaf(f0.y, z1[e0], f0.z));
            d.y = fmaf(f1.x, z0[e0], fmaf(f1.y, z1[e0], f1.z));
            d.z = fmaf(f0.x, z0[e1], fmaf(f0.y, z1[e1], f0.z));
            d.w = fmaf(f1.x, z0[e1], fmaf(f1.y, z1[e1], f1.z));
            out4[idx] = d;
        }
    }
}

extern "C" void kernel_launch(void* const* d_in, const int* in_sizes, int n_in,
                              void* d_out, int out_size)
{
    const float4* x4    = (const float4*)d_in[0];
    const float*  act_w = (const float*)d_in[1];
    const float*  bias_b= (const float*)d_in[2];
    const float*  lin_w = (const float*)d_in[3];
    float4* out4 = (float4*)d_out;

    int n4 = in_sizes[0] / 4;          // float4 count (2 pairs each)

    int per_block = TPB * (EPT / 2);   // float4s per block
    int blocks = (n4 + per_block - 1) / per_block;   // = 1024 for N=2097152
    sympnet_kernel<<<blocks, TPB>>>(x4, act_w, bias_b, lin_w, out4, n4);
}